// round 17
// baseline (speedup 1.0000x reference)
#include <cuda_runtime.h>
#include <cuda_bf16.h>
#include <cuda_fp16.h>
#include <math.h>

// ---------------- problem dims ----------------
#define BATCH   1024
#define TLEN    16000
#define NFFT    400
#define HOP     200
#define NBINS   201
#define NMELS   128
#define NFRAMES 81
#define TSTEPS  79
#define HID     128
#define G4      512
#define R1      (BATCH*NFRAMES)   // 82944
#define R2      (BATCH*TSTEPS)    // 80896

#define KP_DFT  416
#define KP_MEL  224
#define KP_G    128
#define NP_DFT  448
#define KCONV   384

// bf16 split k_gemm dynamic smem (bf16 elems)
#define GEMM_SMEM_ELEMS (2*128*40*2 + 2*64*40*2)   // 30720
#define GEMM_SMEM_BYTES (GEMM_SMEM_ELEMS*2)        // 61440
#define OFF_AL  10240
#define OFF_BH  20480
#define OFF_BL  25600

// fp16 single-term GEMM smem
#define F16_SMEM_ELEMS (2*128*40 + 2*64*40)        // 15360
#define F16_SMEM_BYTES (F16_SMEM_ELEMS*2)          // 30720
#define DOFF_B  10240

// LSTM v6 (fused xW + resident U/W + double-buffered H) smem layout, BYTES
#define UH_STRIDE 136
#define W_STRIDE  136
#define X_STRIDE  136
#define H_STRIDE  264
#define SM_H      (16*H_STRIDE)                    // elems per H buffer (4224)
#define OFFB_UL   69632                            // 256*136*2
#define OFFB_W    139264
#define OFFB_H0   208896
#define OFFB_H1   (208896 + 8448)
#define OFFB_X    (208896 + 16896)
#define LSTM3_SMEM_BYTES (OFFB_X + 16*X_STRIDE*2)  // 230144

// ---------------- scratch ----------------
__device__ float          d_hann[NFFT];
__device__ __half         d_A1dft[(size_t)R1 * KP_DFT];
__device__ __half         d_B1dft[(size_t)NP_DFT * KP_DFT];
__device__ __nv_bfloat16  d_A2mel[(size_t)R1 * 2 * KP_MEL];
__device__ __nv_bfloat16  d_B2mel[(size_t)128 * 2 * KP_MEL];
__device__ __nv_bfloat16  d_melsp[(size_t)R1 * 256];
__device__ __nv_bfloat16  d_B2conv[(size_t)128 * 2 * KCONV];
__device__ __half         d_A1g[(size_t)R2 * KP_G];
__device__ __half         d_W1h[(size_t)G4 * KP_G];
__device__ __half         d_W2h[(size_t)G4 * KP_G];
__device__ __nv_bfloat16  d_U1p[(size_t)G4 * 2 * KP_G];
__device__ __nv_bfloat16  d_U2p[(size_t)G4 * 2 * KP_G];
__device__ float          d_b1p[G4];
__device__ float          d_b2p[G4];
__device__ __half         d_h1h[(size_t)R2 * KP_G];
__device__ float          d_hmean[BATCH * 128];
__device__ float          d_hfc[BATCH * 128];

// ---------------- helpers ----------------
__device__ __forceinline__ float sigf(float x) { return 1.0f / (1.0f + __expf(-x)); }
__device__ __forceinline__ float tanhf_acc(float x) {
    float t = __expf(-2.0f * fabsf(x));
    float r = (1.0f - t) / (1.0f + t);
    return copysignf(r, x);
}
__device__ __forceinline__ void splitw(__nv_bfloat16* P, size_t base, int KpOut, int k, float v) {
    __nv_bfloat16 h = __float2bfloat16(v);
    P[base + k] = h;
    P[base + KpOut + k] = __float2bfloat16(v - __bfloat162float(h));
}
__device__ __forceinline__ unsigned smaddr(const void* p) {
    return (unsigned)__cvta_generic_to_shared(p);
}
__device__ __forceinline__ void cpa16(unsigned dst, const void* src) {
    asm volatile("cp.async.cg.shared.global [%0], [%1], 16;" :: "r"(dst), "l"(src));
}
__device__ __forceinline__ void cpa_commit() { asm volatile("cp.async.commit_group;"); }
__device__ __forceinline__ void mma16816(float* c, const unsigned* a, unsigned b0, unsigned b1) {
    asm volatile(
        "mma.sync.aligned.m16n8k16.row.col.f32.bf16.bf16.f32 "
        "{%0,%1,%2,%3}, {%4,%5,%6,%7}, {%8,%9}, {%0,%1,%2,%3};"
        : "+f"(c[0]), "+f"(c[1]), "+f"(c[2]), "+f"(c[3])
        : "r"(a[0]), "r"(a[1]), "r"(a[2]), "r"(a[3]), "r"(b0), "r"(b1));
}
__device__ __forceinline__ void mma16816h(float* c, const unsigned* a, unsigned b0, unsigned b1) {
    asm volatile(
        "mma.sync.aligned.m16n8k16.row.col.f32.f16.f16.f32 "
        "{%0,%1,%2,%3}, {%4,%5,%6,%7}, {%8,%9}, {%0,%1,%2,%3};"
        : "+f"(c[0]), "+f"(c[1]), "+f"(c[2]), "+f"(c[3])
        : "r"(a[0]), "r"(a[1]), "r"(a[2]), "r"(a[3]), "r"(b0), "r"(b1));
}
// packed gate col n -> original col (slice/gate/unit; same as R15/R16)
__device__ __forceinline__ int gperm(int n) {
    int slice = n >> 5, s = n & 31, gate = s >> 3, u = s & 7;
    return gate * 128 + slice * 8 + u;
}
#define CLUSTER_SYNC() do { \
    asm volatile("barrier.cluster.arrive.aligned;" ::: "memory"); \
    asm volatile("barrier.cluster.wait.aligned;"   ::: "memory"); } while (0)

// ---------------- precompute (fp32 fast math) ----------------
__global__ void k_precompute(const float* __restrict__ conv_w,
                             const float* __restrict__ W1, const float* __restrict__ W2,
                             const float* __restrict__ U1, const float* __restrict__ U2,
                             const float* __restrict__ b1, const float* __restrict__ b2) {
    int tid = blockIdx.x * blockDim.x + threadIdx.x;
    int nth = gridDim.x * blockDim.x;

    for (int k = tid; k < NFFT; k += nth)
        d_hann[k] = 0.5f - 0.5f * cospif((float)k / 200.0f);

    for (int idx = tid; idx < NP_DFT * KP_DFT; idx += nth) {
        int n = idx / KP_DFT, k = idx % KP_DFT;
        float v = 0.f;
        if (n < 2 * NBINS && k < NFFT) {
            int m = n >> 1;
            int ph = (m * k) % 400;
            float s, c;
            sincospif((float)ph / 200.0f, &s, &c);
            v = (n & 1) ? s : c;
        }
        d_B1dft[(size_t)n * KP_DFT + k] = __float2half(v);
    }

    const float mel_max = 2595.0f * log10f(1.0f + 8000.0f / 700.0f);
    for (int idx = tid; idx < 128 * KP_MEL; idx += nth) {
        int m = idx / KP_MEL, k = idx % KP_MEL;
        float v = 0.f;
        if (k < NBINS) {
            float freq = 40.0f * (float)k;
            float f0 = 700.0f * (exp10f((mel_max * (float)(m    ) / 129.0f) / 2595.0f) - 1.0f);
            float f1 = 700.0f * (exp10f((mel_max * (float)(m + 1) / 129.0f) / 2595.0f) - 1.0f);
            float f2 = 700.0f * (exp10f((mel_max * (float)(m + 2) / 129.0f) / 2595.0f) - 1.0f);
            float dn = (freq - f0) / (f1 - f0);
            float up = (f2 - freq) / (f2 - f1);
            float t = fminf(dn, up);
            v = fmaxf(t, 0.0f);
        }
        splitw(d_B2mel, (size_t)m * (2 * KP_MEL), KP_MEL, k, v);
    }

    for (int idx = tid; idx < 128 * KCONV; idx += nth) {
        int o = idx / KCONV, q = idx % KCONV;
        int kk = q >> 7, i = q & 127;
        splitw(d_B2conv, (size_t)o * (2 * KCONV), KCONV, q, conv_w[o * 384 + i * 3 + kk]);
    }

    for (int idx = tid; idx < G4 * KP_G; idx += nth) {
        int n = idx / KP_G, k = idx % KP_G;
        int no = gperm(n);
        d_W1h[(size_t)n * KP_G + k] = __float2half(W1[k * G4 + no]);
        d_W2h[(size_t)n * KP_G + k] = __float2half(W2[k * G4 + no]);
        splitw(d_U1p, (size_t)n * (2 * KP_G), KP_G, k, U1[k * G4 + no]);
        splitw(d_U2p, (size_t)n * (2 * KP_G), KP_G, k, U2[k * G4 + no]);
    }
    for (int n = tid; n < G4; n += nth) {
        int no = gperm(n);
        d_b1p[n] = b1[no];
        d_b2p[n] = b2[no];
    }

    for (int idx = tid; idx < R1 * (KP_MEL - NBINS); idx += nth) {
        int r = idx / (KP_MEL - NBINS), k = NBINS + idx % (KP_MEL - NBINS);
        d_A2mel[(size_t)r * (2 * KP_MEL) + k] = __float2bfloat16(0.f);
        d_A2mel[(size_t)r * (2 * KP_MEL) + KP_MEL + k] = __float2bfloat16(0.f);
    }
}

// ---------------- window -> fp16 A ----------------
__global__ void k_window(const float* __restrict__ x) {
    int f = blockIdx.x, b = blockIdx.y, tid = threadIdx.x;
    size_t row = (size_t)(b * NFRAMES + f) * KP_DFT;
    for (int k = tid; k < KP_DFT; k += blockDim.x) {
        float v = 0.f;
        if (k < NFFT) {
            int p = f * HOP + k - 200;
            int i = (p < 0) ? -p : ((p >= TLEN) ? (2 * TLEN - 2 - p) : p);
            v = x[(size_t)b * TLEN + i] * d_hann[k];
        }
        d_A1dft[row + k] = __float2half(v);
    }
}

// ---------------- single-term fp16 GEMM (DFT, mode 1) ----------------
__global__ void __launch_bounds__(256, 3)
k_gemm16(const __half* __restrict__ A1, const __half* __restrict__ B1,
         int Kp, const float* __restrict__ bias, int mode,
         float* __restrict__ outF, int ldc,
         __nv_bfloat16* __restrict__ outP) {
    extern __shared__ __half smh[];
    __half* AHs = smh;
    __half* BHs = smh + DOFF_B;

    int tid = threadIdx.x, lane = tid & 31, w = tid >> 5;
    int wm = w >> 1, wn = w & 1;
    int m0 = blockIdx.y * 128, n0 = blockIdx.x * 64;
    int g = lane >> 2, t = lane & 3;
    int la_row = tid >> 2, la_kc = (tid & 3) << 3;

    const __half* Abase = A1 + (size_t)m0 * Kp;
    const __half* Bbase = B1 + (size_t)n0 * Kp;

    float acc[2][4][4];
    #pragma unroll
    for (int i = 0; i < 2; i++)
        #pragma unroll
        for (int j = 0; j < 4; j++)
            #pragma unroll
            for (int q = 0; q < 4; q++) acc[i][j][q] = 0.f;

    auto load_chunk = [&](int buf, int kk) {
        int bo = buf * 5120, bo2 = buf * 2560;
        cpa16(smaddr(AHs + bo + la_row * 40 + la_kc),        Abase + (size_t)la_row * Kp + kk + la_kc);
        cpa16(smaddr(AHs + bo + (la_row + 64) * 40 + la_kc), Abase + (size_t)(la_row + 64) * Kp + kk + la_kc);
        cpa16(smaddr(BHs + bo2 + la_row * 40 + la_kc),       Bbase + (size_t)la_row * Kp + kk + la_kc);
        cpa_commit();
    };

    load_chunk(0, 0);

    #pragma unroll 1
    for (int kk = 0; kk < Kp; kk += 32) {
        int buf = (kk >> 5) & 1;
        asm volatile("cp.async.wait_group 0;");
        __syncthreads();
        if (kk + 32 < Kp) load_chunk(buf ^ 1, kk + 32);

        int bo = buf * 5120, bo2 = buf * 2560;
        #pragma unroll
        for (int ko = 0; ko < 32; ko += 16) {
            unsigned ahf[2][4], bhf[4][2];
            #pragma unroll
            for (int i = 0; i < 2; i++) {
                int r = wm * 32 + i * 16;
                ahf[i][0] = *(const unsigned*)&AHs[bo + (r + g) * 40 + ko + 2 * t];
                ahf[i][1] = *(const unsigned*)&AHs[bo + (r + g + 8) * 40 + ko + 2 * t];
                ahf[i][2] = *(const unsigned*)&AHs[bo + (r + g) * 40 + ko + 2 * t + 8];
                ahf[i][3] = *(const unsigned*)&AHs[bo + (r + g + 8) * 40 + ko + 2 * t + 8];
            }
            #pragma unroll
            for (int j = 0; j < 4; j++) {
                int bn = wn * 32 + j * 8 + g;
                bhf[j][0] = *(const unsigned*)&BHs[bo2 + bn * 40 + ko + 2 * t];
                bhf[j][1] = *(const unsigned*)&BHs[bo2 + bn * 40 + ko + 2 * t + 8];
            }
            #pragma unroll
            for (int i = 0; i < 2; i++)
                #pragma unroll
                for (int j = 0; j < 4; j++)
                    mma16816h(acc[i][j], ahf[i], bhf[j][0], bhf[j][1]);
        }
        __syncthreads();
    }

    #pragma unroll
    for (int i = 0; i < 2; i++) {
        int r = m0 + wm * 32 + i * 16 + g;
        #pragma unroll
        for (int j = 0; j < 4; j++) {
            int c = n0 + wn * 32 + j * 8 + 2 * t;
            if (mode == 0) {
                float b0 = bias ? bias[c] : 0.f, b1 = bias ? bias[c + 1] : 0.f;
                outF[(size_t)r * ldc + c]           = acc[i][j][0] + b0;
                outF[(size_t)r * ldc + c + 1]       = acc[i][j][1] + b1;
                outF[(size_t)(r + 8) * ldc + c]     = acc[i][j][2] + b0;
                outF[(size_t)(r + 8) * ldc + c + 1] = acc[i][j][3] + b1;
            } else {
                int k = c >> 1;
                if (k < NBINS) {
                    float p0 = acc[i][j][0] * acc[i][j][0] + acc[i][j][1] * acc[i][j][1];
                    float p1 = acc[i][j][2] * acc[i][j][2] + acc[i][j][3] * acc[i][j][3];
                    splitw(outP, (size_t)r * (2 * KP_MEL), KP_MEL, k, p0);
                    splitw(outP, (size_t)(r + 8) * (2 * KP_MEL), KP_MEL, k, p1);
                }
            }
        }
    }
}

// ---------------- split-bf16 tensor GEMM (mel; proven) ----------------
__global__ void __launch_bounds__(256, 3)
k_gemm(const __nv_bfloat16* __restrict__ A2, const __nv_bfloat16* __restrict__ B2,
       int Kp, const float* __restrict__ bias, int mode,
       float* __restrict__ outF, int ldc, int Nreal,
       __nv_bfloat16* __restrict__ outP, int KpOut) {
    extern __shared__ __nv_bfloat16 smd[];
    __nv_bfloat16* AHs = smd;
    __nv_bfloat16* ALs = smd + OFF_AL;
    __nv_bfloat16* BHs = smd + OFF_BH;
    __nv_bfloat16* BLs = smd + OFF_BL;

    int tid = threadIdx.x, lane = tid & 31, w = tid >> 5;
    int wm = w >> 1, wn = w & 1;
    int m0 = blockIdx.y * 128, n0 = blockIdx.x * 64;
    int g = lane >> 2, t = lane & 3;
    int strideA = 2 * Kp;
    int la_row = tid >> 2, la_kc = (tid & 3) << 3;

    const __nv_bfloat16* Abase = A2 + (size_t)m0 * strideA;
    const __nv_bfloat16* Bbase = B2 + (size_t)n0 * strideA;

    float acc[2][4][4];
    #pragma unroll
    for (int i = 0; i < 2; i++)
        #pragma unroll
        for (int j = 0; j < 4; j++)
            #pragma unroll
            for (int q = 0; q < 4; q++) acc[i][j][q] = 0.f;

    auto load_chunk = [&](int buf, int kk) {
        int bo = buf * 5120, bo2 = buf * 2560;
        cpa16(smaddr(AHs + bo + la_row * 40 + la_kc),        Abase + (size_t)la_row * strideA + kk + la_kc);
        cpa16(smaddr(AHs + bo + (la_row + 64) * 40 + la_kc), Abase + (size_t)(la_row + 64) * strideA + kk + la_kc);
        cpa16(smaddr(ALs + bo + la_row * 40 + la_kc),        Abase + (size_t)la_row * strideA + Kp + kk + la_kc);
        cpa16(smaddr(ALs + bo + (la_row + 64) * 40 + la_kc), Abase + (size_t)(la_row + 64) * strideA + Kp + kk + la_kc);
        cpa16(smaddr(BHs + bo2 + la_row * 40 + la_kc),       Bbase + (size_t)la_row * strideA + kk + la_kc);
        cpa16(smaddr(BLs + bo2 + la_row * 40 + la_kc),       Bbase + (size_t)la_row * strideA + Kp + kk + la_kc);
        cpa_commit();
    };

    load_chunk(0, 0);

    #pragma unroll 1
    for (int kk = 0; kk < Kp; kk += 32) {
        int buf = (kk >> 5) & 1;
        asm volatile("cp.async.wait_group 0;");
        __syncthreads();
        if (kk + 32 < Kp) load_chunk(buf ^ 1, kk + 32);

        int bo = buf * 5120, bo2 = buf * 2560;
        #pragma unroll
        for (int ko = 0; ko < 32; ko += 16) {
            unsigned ahf[2][4], alf[2][4], bhf[4][2], blf[4][2];
            #pragma unroll
            for (int i = 0; i < 2; i++) {
                int r = wm * 32 + i * 16;
                ahf[i][0] = *(const unsigned*)&AHs[bo + (r + g) * 40 + ko + 2 * t];
                ahf[i][1] = *(const unsigned*)&AHs[bo + (r + g + 8) * 40 + ko + 2 * t];
                ahf[i][2] = *(const unsigned*)&AHs[bo + (r + g) * 40 + ko + 2 * t + 8];
                ahf[i][3] = *(const unsigned*)&AHs[bo + (r + g + 8) * 40 + ko + 2 * t + 8];
                alf[i][0] = *(const unsigned*)&ALs[bo + (r + g) * 40 + ko + 2 * t];
                alf[i][1] = *(const unsigned*)&ALs[bo + (r + g + 8) * 40 + ko + 2 * t];
                alf[i][2] = *(const unsigned*)&ALs[bo + (r + g) * 40 + ko + 2 * t + 8];
                alf[i][3] = *(const unsigned*)&ALs[bo + (r + g + 8) * 40 + ko + 2 * t + 8];
            }
            #pragma unroll
            for (int j = 0; j < 4; j++) {
                int bn = wn * 32 + j * 8 + g;
                bhf[j][0] = *(const unsigned*)&BHs[bo2 + bn * 40 + ko + 2 * t];
                bhf[j][1] = *(const unsigned*)&BHs[bo2 + bn * 40 + ko + 2 * t + 8];
                blf[j][0] = *(const unsigned*)&BLs[bo2 + bn * 40 + ko + 2 * t];
                blf[j][1] = *(const unsigned*)&BLs[bo2 + bn * 40 + ko + 2 * t + 8];
            }
            #pragma unroll
            for (int i = 0; i < 2; i++)
                #pragma unroll
                for (int j = 0; j < 4; j++) {
                    mma16816(acc[i][j], ahf[i], bhf[j][0], bhf[j][1]);
                    mma16816(acc[i][j], ahf[i], blf[j][0], blf[j][1]);
                    mma16816(acc[i][j], alf[i], bhf[j][0], bhf[j][1]);
                }
        }
        __syncthreads();
    }

    #pragma unroll
    for (int i = 0; i < 2; i++) {
        int r = m0 + wm * 32 + i * 16 + g;
        #pragma unroll
        for (int j = 0; j < 4; j++) {
            int c = n0 + wn * 32 + j * 8 + 2 * t;
            float v00 = acc[i][j][0], v01 = acc[i][j][1];
            float v10 = acc[i][j][2], v11 = acc[i][j][3];
            if (mode == 0) {
                float b0 = bias ? bias[c] : 0.f, b1 = bias ? bias[c + 1] : 0.f;
                outF[(size_t)r * ldc + c]           = v00 + b0;
                outF[(size_t)r * ldc + c + 1]       = v01 + b1;
                outF[(size_t)(r + 8) * ldc + c]     = v10 + b0;
                outF[(size_t)(r + 8) * ldc + c + 1] = v11 + b1;
            } else {
                float b0 = bias ? bias[c] : 0.f, b1 = bias ? bias[c + 1] : 0.f;
                splitw(outP, (size_t)r * (2 * KpOut), KpOut, c, v00 + b0);
                splitw(outP, (size_t)r * (2 * KpOut), KpOut, c + 1, v01 + b1);
                splitw(outP, (size_t)(r + 8) * (2 * KpOut), KpOut, c, v10 + b0);
                splitw(outP, (size_t)(r + 8) * (2 * KpOut), KpOut, c + 1, v11 + b1);
            }
        }
    }
}

// ---------------- conv GEMM: shifted rows, 9 segments, fp16 single output ----------------
__global__ void __launch_bounds__(256, 3)
k_gemm_conv(const __nv_bfloat16* __restrict__ Msp, const __nv_bfloat16* __restrict__ B2,
            const float* __restrict__ bias, __half* __restrict__ outH) {
    __shared__ __nv_bfloat16 As[2][128][40];
    __shared__ __nv_bfloat16 Bs[2][64][40];
    int tid = threadIdx.x, lane = tid & 31, w = tid >> 5;
    int wm = w >> 1, wn = w & 1;
    int m0 = blockIdx.y * 128, n0 = blockIdx.x * 64;
    int g = lane >> 2, t = lane & 3;
    int la_row = tid >> 2, la_kc = (tid & 3) << 3;

    int gm0 = m0 + la_row, gm1 = m0 + la_row + 64;
    int sr0 = gm0 + 2 * (gm0 / TSTEPS);
    int sr1 = gm1 + 2 * (gm1 / TSTEPS);

    float acc[2][4][4];
    #pragma unroll
    for (int i = 0; i < 2; i++)
        #pragma unroll
        for (int j = 0; j < 4; j++)
            #pragma unroll
            for (int q = 0; q < 4; q++) acc[i][j][q] = 0.f;

    #pragma unroll 1
    for (int s = 0; s < 9; s++) {
        int split = s / 3, shift = s % 3;
        int aoff = (split == 2) ? 128 : 0;
        int boff = ((split == 1) ? KCONV : 0) + shift * 128;
        const __nv_bfloat16* A0 = Msp + (size_t)(sr0 + shift) * 256 + aoff;
        const __nv_bfloat16* A1 = Msp + (size_t)(sr1 + shift) * 256 + aoff;
        const __nv_bfloat16* Bb = B2 + (size_t)n0 * (2 * KCONV) + boff;

        cpa16(smaddr(&As[0][la_row][la_kc]),      A0 + la_kc);
        cpa16(smaddr(&As[0][la_row + 64][la_kc]), A1 + la_kc);
        cpa16(smaddr(&Bs[0][la_row][la_kc]),      Bb + (size_t)la_row * (2 * KCONV) + la_kc);
        cpa_commit();
        #pragma unroll 1
        for (int kk = 0; kk < 128; kk += 32) {
            int buf = (kk >> 5) & 1;
            asm volatile("cp.async.wait_group 0;");
            __syncthreads();
            if (kk + 32 < 128) {
                int nb = buf ^ 1, kn = kk + 32;
                cpa16(smaddr(&As[nb][la_row][la_kc]),      A0 + kn + la_kc);
                cpa16(smaddr(&As[nb][la_row + 64][la_kc]), A1 + kn + la_kc);
                cpa16(smaddr(&Bs[nb][la_row][la_kc]),      Bb + (size_t)la_row * (2 * KCONV) + kn + la_kc);
                cpa_commit();
            }
            #pragma unroll
            for (int ko = 0; ko < 32; ko += 16) {
                unsigned a[2][4], bfr[4][2];
                #pragma unroll
                for (int i = 0; i < 2; i++) {
                    int r = wm * 32 + i * 16;
                    a[i][0] = *(const unsigned*)&As[buf][r + g][ko + 2 * t];
                    a[i][1] = *(const unsigned*)&As[buf][r + g + 8][ko + 2 * t];
                    a[i][2] = *(const unsigned*)&As[buf][r + g][ko + 2 * t + 8];
                    a[i][3] = *(const unsigned*)&As[buf][r + g + 8][ko + 2 * t + 8];
                }
                #pragma unroll
                for (int j = 0; j < 4; j++) {
                    int bn = wn * 32 + j * 8 + g;
                    bfr[j][0] = *(const unsigned*)&Bs[buf][bn][ko + 2 * t];
                    bfr[j][1] = *(const unsigned*)&Bs[buf][bn][ko + 2 * t + 8];
                }
                #pragma unroll
                for (int i = 0; i < 2; i++)
                    #pragma unroll
                    for (int j = 0; j < 4; j++)
                        mma16816(acc[i][j], a[i], bfr[j][0], bfr[j][1]);
            }
            __syncthreads();
        }
    }

    #pragma unroll
    for (int i = 0; i < 2; i++) {
        int r = m0 + wm * 32 + i * 16 + g;
        #pragma unroll
        for (int j = 0; j < 4; j++) {
            int c = n0 + wn * 32 + j * 8 + 2 * t;
            float b0 = bias[c], b1 = bias[c + 1];
            outH[(size_t)r * KP_G + c]           = __float2half(acc[i][j][0] + b0);
            outH[(size_t)r * KP_G + c + 1]       = __float2half(acc[i][j][1] + b1);
            outH[(size_t)(r + 8) * KP_G + c]     = __float2half(acc[i][j][2] + b0);
            outH[(size_t)(r + 8) * KP_G + c + 1] = __float2half(acc[i][j][3] + b1);
        }
    }
}

// ---------------- LSTM v6: fused x@W, resident U+W, double-buffered H, 1 cluster sync/step ----------------
__global__ void __cluster_dims__(2, 1, 1) __launch_bounds__(256)
k_lstm_mma(const __half* __restrict__ xg, const __nv_bfloat16* __restrict__ Up,
           const __half* __restrict__ Wp, const float* __restrict__ bias,
           __half* __restrict__ hexp, float* __restrict__ hmean) {
    extern __shared__ char smc[];
    __nv_bfloat16* Uh   = (__nv_bfloat16*)smc;                 // [256][136]
    __nv_bfloat16* Ulr  = (__nv_bfloat16*)(smc + OFFB_UL);     // [256][136]
    __half*        Whs  = (__half*)(smc + OFFB_W);             // [256][136]
    __nv_bfloat16* Hsp0 = (__nv_bfloat16*)(smc + OFFB_H0);     // [16][264]
    __nv_bfloat16* Hsp1 = (__nv_bfloat16*)(smc + OFFB_H1);     // [16][264]
    __half*        Xb   = (__half*)(smc + OFFB_X);             // [16][136]

    int tid = threadIdx.x, lane = tid & 31, w = tid >> 5;
    int g = lane >> 2, tq = lane & 3;
    unsigned rank;
    asm("mov.u32 %0, %%cluster_ctarank;" : "=r"(rank));
    int b0 = (blockIdx.x >> 1) * 16;
    int nbase_l = w * 32;
    int gbase = (int)rank * 256 + nbase_l;
    int slice = (int)rank * 8 + w;
    const __nv_bfloat16* UpC = Up + (size_t)((int)rank * 256) * 256;
    const __half* WpC = Wp + (size_t)((int)rank * 256) * KP_G;

    unsigned peerH0;
    asm("mapa.shared::cluster.u32 %0, %1, %2;"
        : "=r"(peerH0) : "r"(smaddr(Hsp0)), "r"(1u - rank));

    // resident loads: Uh (hi), Ulr (lo), Whs (fp16); zero H buffers
    for (int idx = tid; idx < 256 * 16; idx += 256) {
        int n = idx >> 4, j = idx & 15;
        *(uint4*)(Uh  + n * UH_STRIDE + j * 8) = *(const uint4*)(UpC + (size_t)n * 256 + j * 8);
        *(uint4*)(Ulr + n * UH_STRIDE + j * 8) = *(const uint4*)(UpC + (size_t)n * 256 + 128 + j * 8);
    }
    for (int idx = tid; idx < 256 * 16; idx += 256) {
        int n = idx >> 4, j = idx & 15;
        if (j < 16) {
            // 128 fp16 per row = 16 x 8-halves
            *(uint4*)(Whs + n * W_STRIDE + j * 8) = *(const uint4*)(WpC + (size_t)n * KP_G + j * 8);
        }
    }
    for (int idx = tid; idx < 2 * SM_H; idx += 256) Hsp0[idx] = __float2bfloat16(0.f);

    // prefetch x_0
    {
        int row = tid >> 4, seg = tid & 15;
        cpa16(smaddr(Xb + row * X_STRIDE + seg * 8),
              xg + ((size_t)(b0 + row) * TSTEPS + 0) * KP_G + seg * 8);
        cpa_commit();
    }

    float cst[4], hsum[4];
    #pragma unroll
    for (int i = 0; i < 4; i++) { cst[i] = 0.f; hsum[i] = 0.f; }

    for (int t = 0; t < TSTEPS; t++) {
        asm volatile("cp.async.wait_group 0;");   // x_t copies done (this thread)
        CLUSTER_SYNC();                           // publish x_t + h(t-1) everywhere

        // acc init = bias (per packed col)
        float acc[4][4];
        #pragma unroll
        for (int bn = 0; bn < 4; bn++) {
            float2 bv = *(const float2*)&bias[gbase + bn * 8 + 2 * tq];
            acc[bn][0] = bv.x; acc[bn][1] = bv.y;
            acc[bn][2] = bv.x; acc[bn][3] = bv.y;
        }

        // phase 1: x_t @ W (fp16), k = 0..127 in 8 sequential k16 steps
        #pragma unroll
        for (int c = 0; c < 8; c++) {
            int ko = c * 16 + 2 * tq;
            unsigned ax[4];
            ax[0] = *(const unsigned*)&Xb[g * X_STRIDE + ko];
            ax[1] = *(const unsigned*)&Xb[(g + 8) * X_STRIDE + ko];
            ax[2] = *(const unsigned*)&Xb[g * X_STRIDE + ko + 8];
            ax[3] = *(const unsigned*)&Xb[(g + 8) * X_STRIDE + ko + 8];
            #pragma unroll
            for (int bn = 0; bn < 4; bn++) {
                const __half* bpw = Whs + (nbase_l + bn * 8 + g) * W_STRIDE + ko;
                mma16816h(acc[bn], ax, *(const unsigned*)bpw, *(const unsigned*)(bpw + 8));
            }
        }
        __syncthreads();   // all x_t reads complete before overwrite
        if (t + 1 < TSTEPS) {
            int row = tid >> 4, seg = tid & 15;
            cpa16(smaddr(Xb + row * X_STRIDE + seg * 8),
                  xg + ((size_t)(b0 + row) * TSTEPS + (t + 1)) * KP_G + seg * 8);
            cpa_commit();
        }

        // phase 2: h(t-1) @ U (bf16 split)
        const __nv_bfloat16* Hrd = ((t & 1) ? Hsp0 : Hsp1);
        #pragma unroll 1
        for (int c = 0; c < 8; c++) {
            int ko = c * 16 + 2 * tq;
            unsigned ah[4], al[4];
            ah[0] = *(const unsigned*)&Hrd[g * H_STRIDE + ko];
            ah[1] = *(const unsigned*)&Hrd[(g + 8) * H_STRIDE + ko];
            ah[2] = *(const unsigned*)&Hrd[g * H_STRIDE + ko + 8];
            ah[3] = *(const unsigned*)&Hrd[(g + 8) * H_STRIDE + ko + 8];
            al[0] = *(const unsigned*)&Hrd[g * H_STRIDE + 128 + ko];
            al[1] = *(const unsigned*)&Hrd[(g + 8) * H_STRIDE + 128 + ko];
            al[2] = *(const unsigned*)&Hrd[g * H_STRIDE + 128 + ko + 8];
            al[3] = *(const unsigned*)&Hrd[(g + 8) * H_STRIDE + 128 + ko + 8];
            #pragma unroll
            for (int bn = 0; bn < 4; bn++) {
                int n = nbase_l + bn * 8 + g;
                const __nv_bfloat16* bph = Uh + n * UH_STRIDE + ko;
                unsigned h0 = *(const unsigned*)bph;
                unsigned h1 = *(const unsigned*)(bph + 8);
                mma16816(acc[bn], ah, h0, h1);
                mma16816(acc[bn], al, h0, h1);
                const __nv_bfloat16* bpl = Ulr + n * UH_STRIDE + ko;
                unsigned l0 = *(const unsigned*)bpl;
                unsigned l1 = *(const unsigned*)(bpl + 8);
                mma16816(acc[bn], ah, l0, l1);
            }
        }

        // elementwise; write h(t) into buf[t&1] locally + peer (DSMEM)
        __nv_bfloat16* Hwr = ((t & 1) ? Hsp1 : Hsp0);
        unsigned peerWr = peerH0 + (unsigned)((t & 1) ? SM_H * 2 : 0);
        #pragma unroll
        for (int q2 = 0; q2 < 2; q2++) {
            int r_ = g + 8 * q2;
            float hv[2];
            #pragma unroll
            for (int par = 0; par < 2; par++) {
                int qq = q2 * 2 + par;
                int ci = q2 * 2 + par;
                float gi = acc[0][qq], gf = acc[1][qq], gg = acc[2][qq], go = acc[3][qq];
                float c = sigf(gf) * cst[ci] + sigf(gi) * tanhf_acc(gg);
                float h = sigf(go) * tanhf_acc(c);
                cst[ci] = c;
                hsum[ci] += h;
                hv[par] = h;
            }
            int ug0 = slice * 8 + 2 * tq;
            __nv_bfloat16 h0h = __float2bfloat16(hv[0]);
            __nv_bfloat16 h1h = __float2bfloat16(hv[1]);
            __nv_bfloat16 h0l = __float2bfloat16(hv[0] - __bfloat162float(h0h));
            __nv_bfloat16 h1l = __float2bfloat16(hv[1] - __bfloat162float(h1h));
            unsigned hip = ((unsigned)__bfloat16_as_ushort(h1h) << 16) | __bfloat16_as_ushort(h0h);
            unsigned lop = ((unsigned)__bfloat16_as_ushort(h1l) << 16) | __bfloat16_as_ushort(h0l);
            int offHi = r_ * H_STRIDE + ug0;
            int offLo = offHi + 128;
            *(unsigned*)&Hwr[offHi] = hip;
            *(unsigned*)&Hwr[offLo] = lop;
            asm volatile("st.shared::cluster.u32 [%0], %1;" :: "r"(peerWr + offHi * 2), "r"(hip) : "memory");
            asm volatile("st.shared::cluster.u32 [%0], %1;" :: "r"(peerWr + offLo * 2), "r"(lop) : "memory");
            if (hexp) {
                unsigned hp = ((unsigned)__half_as_ushort(__float2half(hv[1])) << 16)
                            | __half_as_ushort(__float2half(hv[0]));
                size_t row2 = ((size_t)(b0 + r_) * TSTEPS + t) * KP_G;
                *(unsigned*)&hexp[row2 + ug0] = hp;
            }
        }
    }

    if (hmean) {
        #pragma unroll
        for (int q2 = 0; q2 < 2; q2++)
            #pragma unroll
            for (int par = 0; par < 2; par++) {
                int ci = q2 * 2 + par;
                int ug = slice * 8 + 2 * tq + par;
                hmean[(size_t)(b0 + g + 8 * q2) * 128 + ug] = hsum[ci] * (1.0f / (float)TSTEPS);
            }
    }
    CLUSTER_SYNC();   // no CTA exits while peer DSMEM stores may be in flight
}

// ---------------- small fp32 SGEMM for fc/proj ----------------
__global__ void k_sgemm(const float* __restrict__ A, const float* __restrict__ Bm,
                        float* __restrict__ C, const float* __restrict__ bias,
                        int M, int N, int K) {
    __shared__ float As[8][68];
    __shared__ float Bs[8][64];
    int tid = threadIdx.x;
    int m0 = blockIdx.y * 64, n0 = blockIdx.x * 64;
    int tm = tid & 15, tn = tid >> 4;
    float acc[4][8];
    #pragma unroll
    for (int i = 0; i < 4; i++)
        #pragma unroll
        for (int j = 0; j < 8; j++) acc[i][j] = 0.f;
    for (int kk = 0; kk < K; kk += 8) {
        #pragma unroll
        for (int i = 0; i < 4; i++) {
            int l = tid + i * 128, m = l >> 3, k = l & 7;
            int gm = m0 + m, gk = kk + k;
            As[k][m] = (gm < M && gk < K) ? A[(size_t)gm * K + gk] : 0.f;
        }
        #pragma unroll
        for (int i = 0; i < 4; i++) {
            int l = tid + i * 128, k = l >> 6, n = l & 63;
            int gk = kk + k, gn = n0 + n;
            Bs[k][n] = (gk < K && gn < N) ? Bm[(size_t)gk * N + gn] : 0.f;
        }
        __syncthreads();
        #pragma unroll
        for (int k = 0; k < 8; k++) {
            float a[4], bv[8];
            #pragma unroll
            for (int i = 0; i < 4; i++) a[i] = As[k][tm * 4 + i];
            #pragma unroll
            for (int j = 0; j < 8; j++) bv[j] = Bs[k][tn * 8 + j];
            #pragma unroll
            for (int i = 0; i < 4; i++)
                #pragma unroll
                for (int j = 0; j < 8; j++) acc[i][j] += a[i] * bv[j];
        }
        __syncthreads();
    }
    #pragma unroll
    for (int i = 0; i < 4; i++) {
        int gm = m0 + tm * 4 + i;
        if (gm >= M) continue;
        #pragma unroll
        for (int j = 0; j < 8; j++) {
            int gn = n0 + tn * 8 + j;
            if (gn < N) C[(size_t)gm * N + gn] = acc[i][j] + (bias ? bias[gn] : 0.f);
        }
    }
}

// ---------------- launch ----------------
extern "C" void kernel_launch(void* const* d_in, const int* in_sizes, int n_in,
                              void* d_out, int out_size) {
    const float* x      = (const float*)d_in[0];
    const float* conv_w = (const float*)d_in[1];
    const float* conv_b = (const float*)d_in[2];
    const float* W1     = (const float*)d_in[3];
    const float* U1     = (const float*)d_in[4];
    const float* b1     = (const float*)d_in[5];
    const float* W2     = (const float*)d_in[6];
    const float* U2     = (const float*)d_in[7];
    const float* b2     = (const float*)d_in[8];
    const float* fc1_w  = (const float*)d_in[9];
    const float* fc1_b  = (const float*)d_in[10];
    const float* proj_w = (const float*)d_in[11];
    const float* proj_b = (const float*)d_in[12];
    float* out = (float*)d_out;

    __half *pA1dft, *pB1dft, *pA1g, *pW1h, *pW2h, *pH1h;
    __nv_bfloat16 *pA2mel, *pB2mel, *pMelsp, *pB2conv, *pU1p, *pU2p;
    float *pHmean, *pHfc, *pB1p, *pB2p;
    cudaGetSymbolAddress((void**)&pA1dft,  d_A1dft);
    cudaGetSymbolAddress((void**)&pB1dft,  d_B1dft);
    cudaGetSymbolAddress((void**)&pA2mel,  d_A2mel);
    cudaGetSymbolAddress((void**)&pB2mel,  d_B2mel);
    cudaGetSymbolAddress((void**)&pMelsp,  d_melsp);
    cudaGetSymbolAddress((void**)&pB2conv, d_B2conv);
    cudaGetSymbolAddress((void**)&pA1g,    d_A1g);
    cudaGetSymbolAddress((void**)&pW1h,    d_W1h);
    cudaGetSymbolAddress((void**)&pW2h,    d_W2h);
    cudaGetSymbolAddress((void**)&pU1p,    d_U1p);
    cudaGetSymbolAddress((void**)&pU2p,    d_U2p);
    cudaGetSymbolAddress((void**)&pH1h,    d_h1h);
    cudaGetSymbolAddress((void**)&pHmean,  d_hmean);
    cudaGetSymbolAddress((void**)&pHfc,    d_hfc);
    cudaGetSymbolAddress((void**)&pB1p,    d_b1p);
    cudaGetSymbolAddress((void**)&pB2p,    d_b2p);

    cudaFuncSetAttribute(k_lstm_mma, cudaFuncAttributeMaxDynamicSharedMemorySize, LSTM3_SMEM_BYTES);
    cudaFuncSetAttribute(k_gemm,     cudaFuncAttributeMaxDynamicSharedMemorySize, GEMM_SMEM_BYTES);
    cudaFuncSetAttribute(k_gemm16,   cudaFuncAttributeMaxDynamicSharedMemorySize, F16_SMEM_BYTES);

    k_precompute<<<128, 256>>>(conv_w, W1, W2, U1, U2, b1, b2);
    k_window<<<dim3(NFRAMES, BATCH), 256>>>(x);

    // DFT (fp16 single) -> power split-pack into A2mel
    k_gemm16<<<dim3(NP_DFT / 64, R1 / 128), 256, F16_SMEM_BYTES>>>(
        pA1dft, pB1dft, KP_DFT, nullptr, 1, nullptr, 0, pA2mel);
    // mel (bf16 split) -> split pack
    k_gemm<<<dim3(2, R1 / 128), 256, GEMM_SMEM_BYTES>>>(
        pA2mel, pB2mel, KP_MEL, nullptr, 2, nullptr, 0, NMELS, pMelsp, 128);
    // conv (bf16 split, shifted rows) -> fp16 single into A1g
    k_gemm_conv<<<dim3(2, R2 / 128), 256>>>(pMelsp, pB2conv, conv_b, pA1g);
    // LSTM layer 1 (fused x@W + h@U), exports h1 fp16
    k_lstm_mma<<<(BATCH / 16) * 2, 256, LSTM3_SMEM_BYTES>>>(
        pA1g, pU1p, pW1h, pB1p, pH1h, nullptr);
    // LSTM layer 2 (fused), produces hmean
    k_lstm_mma<<<(BATCH / 16) * 2, 256, LSTM3_SMEM_BYTES>>>(
        pH1h, pU2p, pW2h, pB2p, nullptr, pHmean);

    k_sgemm<<<dim3(2, BATCH / 64), 128>>>(pHmean, fc1_w, pHfc, fc1_b, BATCH, 128, 128);
    k_sgemm<<<dim3(1, BATCH / 64), 128>>>(pHfc, proj_w, out, proj_b, BATCH, 35, 128);
}